// round 14
// baseline (speedup 1.0000x reference)
#include <cuda_runtime.h>
#include <cuda_bf16.h>

// RNN_72541997629806: 5-layer stacked LSTM (H=4), SEQ=610, BATCH=128,
// per-t Linear(4->1) + final FC [5,610] -> out [128,5].
//
// R14: R13 champion (55.8us) with the publish path stripped bare:
//   - stage 0 reads x directly from SMEM (one off-chain select on its PA
//     operand; stage-0 wiB columns are zero so PB is don't-care)
//   - injection lanes deleted; publish is raw hpub=hn (no selects on the
//     h-recurrence between cell output and next round's shuffles)
//   - vector LDS: x via LDS.128/round, FC weight pairs via LDS.64
//   One warp per batch element (128 x 32); 2 timesteps per shuffle round;
//   deferred FC in the shuffle shadow; packed fma.rn.f32x2 gates;
//   gate MUFU order g2,g1,g0,g3; zero-padded SMEM; select-free steady loop.

#define SEQ 610
#define BATCH 128
#define ROUNDS 310           // r = 0..309 ; stage5 t1 = 2*309-10+1 = 609
#define XS_N 624
#define WFC_N 624            // valid data at [10, 620)

typedef unsigned long long ull;

__device__ __forceinline__ float tanh_fast(float x) {
    float y;
    asm("tanh.approx.f32 %0, %1;" : "=f"(y) : "f"(x));
    return y;
}
__device__ __forceinline__ ull pk2(float lo, float hi) {
    ull r; asm("mov.b64 %0, {%1, %2};" : "=l"(r) : "f"(lo), "f"(hi)); return r;
}
__device__ __forceinline__ ull fma2(ull a, ull b, ull c) {
    ull d; asm("fma.rn.f32x2 %0, %1, %2, %3;" : "=l"(d) : "l"(a), "l"(b), "l"(c)); return d;
}
__device__ __forceinline__ ull mul2(ull a, ull b) {
    ull d; asm("mul.rn.f32x2 %0, %1, %2;" : "=l"(d) : "l"(a), "l"(b)); return d;
}
__device__ __forceinline__ ull add2(ull a, ull b) {
    ull d; asm("add.rn.f32x2 %0, %1, %2;" : "=l"(d) : "l"(a), "l"(b)); return d;
}
__device__ __forceinline__ float hadd2(ull v) {
    float lo, hi; asm("mov.b64 {%0, %1}, %2;" : "=f"(lo), "=f"(hi) : "l"(v)); return lo + hi;
}

__global__ __launch_bounds__(32, 1)
void lstm_warp_kernel(const float* __restrict__ x,      // [128,610,2]
                      const float* __restrict__ w_ih0,  // [16,2]
                      const float* __restrict__ w_ih,   // [4,16,4]
                      const float* __restrict__ w_hh,   // [5,16,4]
                      const float* __restrict__ b_ih,   // [5,16]
                      const float* __restrict__ b_hh,   // [5,16]
                      const float* __restrict__ w_lin,  // [1,4]
                      const float* __restrict__ b_lin,  // [1]
                      const float* __restrict__ w_fc,   // [5,610]
                      const float* __restrict__ b_fc,   // [5]
                      float* __restrict__ out)          // [128,5]
{
    const int lane  = threadIdx.x;
    const int stage = lane >> 2;             // 0..7
    const int j     = lane & 3;
    const int b     = blockIdx.x;
    const int pbase = (lane - 4) & 28;       // base lane of previous stage quad
    const bool isS0 = (stage == 0);

    // ---- packed per-lane weights (i/f/o pre-scaled 0.5, sigmoid-via-tanh) ----
    ull wiA0=0,wiA1=0,wiA2=0,wiA3=0, wiB0=0,wiB1=0,wiB2=0,wiB3=0;
    ull whA0=0,whA1=0,whA2=0,whA3=0, whB0=0,whB1=0,whB2=0,whB3=0;
    ull bp0=0, bp1=0, bp2=0, bp3=0;

    if (stage <= 4) {
        #define LQ(q, WIA, WIB, WHA, WHB, BP) do {                                 \
            const int   r  = (q) * 4 + j;                                          \
            const float sc = ((q) == 2) ? 1.0f : 0.5f;                             \
            float w0, w1, w2, w3;                                                  \
            if (stage == 0) {                                                      \
                w0 = sc * w_ih0[r * 2 + 0];  w1 = sc * w_ih0[r * 2 + 1];           \
                w2 = 0.0f;                   w3 = 0.0f;                            \
            } else {                                                               \
                const float* wp = w_ih + (((stage - 1) * 16) + r) * 4;             \
                w0 = sc * wp[0]; w1 = sc * wp[1]; w2 = sc * wp[2]; w3 = sc * wp[3];\
            }                                                                      \
            WIA = pk2(w0, w1);  WIB = pk2(w2, w3);                                 \
            const float* hp = w_hh + ((stage * 16) + r) * 4;                       \
            WHA = pk2(sc * hp[j ^ 0], sc * hp[j ^ 1]);                             \
            WHB = pk2(sc * hp[j ^ 2], sc * hp[j ^ 3]);                             \
            BP  = pk2(sc * (b_ih[stage * 16 + r] + b_hh[stage * 16 + r]), 0.0f);   \
        } while (0)
        LQ(0, wiA0, wiB0, whA0, whB0, bp0);
        LQ(1, wiA1, wiB1, whA1, whB1, bp1);
        LQ(2, wiA2, wiB2, whA2, whB2, bp2);
        LQ(3, wiA3, wiB3, whA3, whB3, bp3);
        #undef LQ
    } else if (stage == 5) {
        wiA0 = pk2(w_lin[0], w_lin[1]);
        wiB0 = pk2(w_lin[2], w_lin[3]);
        bp0  = pk2(b_lin[0], 0.0f);
    }

    // ---- SMEM staging ----
    __shared__ __align__(16) float2 xs2[XS_N];   // [0..609]=x, rest 0
    __shared__ __align__(8)  float  wfc_s[5][WFC_N];  // [10..619]=w_fc row, rest 0
    {
        const float2* xb2 = reinterpret_cast<const float2*>(x + (size_t)b * SEQ * 2);
        for (int i = lane; i < XS_N; i += 32)
            xs2[i] = (i < SEQ) ? xb2[i] : make_float2(0.0f, 0.0f);
        #pragma unroll
        for (int r = 0; r < 5; ++r)
            for (int i = lane; i < WFC_N; i += 32)
                wfc_s[r][i] = (i >= 10 && i < SEQ + 10) ? w_fc[r * SEQ + (i - 10)] : 0.0f;
    }
    __syncwarp();

    const float* wA = wfc_s[(stage == 5) ? j : 0];
    const float* w4 = wfc_s[4];
    float accA = (stage == 5) ? b_fc[j] : 0.0f;
    float accB = (lane == 20) ? b_fc[4] : 0.0f;

    // ---- state (no injection lanes; publishes are raw cell outputs) ----
    float hpubA = 0.0f, hpubB = 0.0f, cj = 0.0f;
    float pg0 = 0.0f, pg1 = 0.0f;           // previous round's g0 values (deferred FC)

    // one LSTM cell; MUFU order: g2 (gt), g1 (f), g0 (i), g3 (o, last)
    #define CELL(PA, PB, HA, HB, CN, HN, G0OUT) do {                               \
        const float g2 = hadd2(add2(fma2(whA2, HA, fma2(wiA2, PA, bp2)),           \
                                    fma2(whB2, HB, mul2(wiB2, PB))));              \
        const float g1 = hadd2(add2(fma2(whA1, HA, fma2(wiA1, PA, bp1)),           \
                                    fma2(whB1, HB, mul2(wiB1, PB))));              \
        const float g0 = hadd2(add2(fma2(whA0, HA, fma2(wiA0, PA, bp0)),           \
                                    fma2(whB0, HB, mul2(wiB0, PB))));              \
        const float g3 = hadd2(add2(fma2(whA3, HA, fma2(wiA3, PA, bp3)),           \
                                    fma2(whB3, HB, mul2(wiB3, PB))));              \
        const float gt = tanh_fast(g2);                                            \
        const float fg = fmaf(0.5f, tanh_fast(g1), 0.5f);                          \
        const float ig = fmaf(0.5f, tanh_fast(g0), 0.5f);                          \
        const float og = fmaf(0.5f, tanh_fast(g3), 0.5f);                          \
        CN = fmaf(fg, cj, ig * gt);                                                \
        HN = og * tanh_fast(CN);                                                   \
        G0OUT = g0;                                                                \
    } while (0)

    // one round = two timesteps t0 = 2r - 2*stage, t1 = t0+1.
    // Order: shuffles -> (shadow) deferred FC of prev round + x load -> cells.
    #define ROUND(r, GUARD) do {                                                   \
        const int i0 = 2 * (r);                                                    \
        /* round-start shuffles (all parallel off hpubA/hpubB) */                  \
        const float ob1 = __shfl_xor_sync(0xffffffffu, hpubB, 1);                  \
        const float ob2 = __shfl_xor_sync(0xffffffffu, hpubB, 2);                  \
        const float ob3 = __shfl_xor_sync(0xffffffffu, hpubB, 3);                  \
        const float pA0 = __shfl_sync(0xffffffffu, hpubA, pbase);                  \
        const float pA1 = __shfl_sync(0xffffffffu, hpubA, pbase + 1);              \
        const float pA2 = __shfl_sync(0xffffffffu, hpubA, pbase + 2);              \
        const float pA3 = __shfl_sync(0xffffffffu, hpubA, pbase + 3);              \
        const float pB0 = __shfl_sync(0xffffffffu, hpubB, pbase);                  \
        const float pB1 = __shfl_sync(0xffffffffu, hpubB, pbase + 1);              \
        const float pB2 = __shfl_sync(0xffffffffu, hpubB, pbase + 2);              \
        const float pB3 = __shfl_sync(0xffffffffu, hpubB, pbase + 3);              \
        /* shuffle shadow: deferred FC acc of PREVIOUS round + x load */           \
        const int ip = GUARD ? ((r) > 0 ? i0 - 2 : 0) : (i0 - 2);                  \
        const float2 wfa = *reinterpret_cast<const float2*>(&wA[ip]);              \
        const float2 wf4 = *reinterpret_cast<const float2*>(&w4[ip]);              \
        accA = fmaf(wfa.x, pg0, accA);                                             \
        accA = fmaf(wfa.y, pg1, accA);                                             \
        accB = fmaf(wf4.x, pg0, accB);                                             \
        accB = fmaf(wf4.y, pg1, accB);                                             \
        const float4 xq = *reinterpret_cast<const float4*>(&xs2[i0]);              \
        /* stage-0 PA override (off-chain select; stage-0 wiB == 0 so PB is */     \
        /* don't-care) */                                                          \
        const ull PAc0 = isS0 ? pk2(xq.x, xq.y) : pk2(pA0, pA1);                   \
        const ull PAc1 = isS0 ? pk2(xq.z, xq.w) : pk2(pB0, pB1);                   \
        /* cell t0: own h quad = (hpubB, ob1..3) = h(t0-1) */                      \
        float cn0, hn0, g0c0;                                                      \
        CELL(PAc0, pk2(pA2, pA3), pk2(hpubB, ob1), pk2(ob2, ob3),                  \
             cn0, hn0, g0c0);                                                      \
        float hAn;                                                                 \
        if (GUARD) {                                                               \
            const bool tv = (r) >= stage;                                          \
            cj  = tv ? cn0 : cj;                                                   \
            hAn = tv ? hn0 : 0.0f;                                                 \
        } else { cj = cn0; hAn = hn0; }                                            \
        /* intra-round gather of h(t0) */                                          \
        const float a1 = __shfl_xor_sync(0xffffffffu, hAn, 1);                     \
        const float a2 = __shfl_xor_sync(0xffffffffu, hAn, 2);                     \
        const float a3 = __shfl_xor_sync(0xffffffffu, hAn, 3);                     \
        /* cell t1 */                                                              \
        float cn1, hn1, g0c1;                                                      \
        CELL(PAc1, pk2(pB2, pB3), pk2(hAn, a1), pk2(a2, a3),                       \
             cn1, hn1, g0c1);                                                      \
        float hBn;                                                                 \
        if (GUARD) {                                                               \
            const bool tv = (r) >= stage;                                          \
            cj  = tv ? cn1 : cj;                                                   \
            hBn = tv ? hn1 : 0.0f;                                                 \
        } else { cj = cn1; hBn = hn1; }                                            \
        /* carry g0s to next round's shuffle shadow; raw publish */                \
        pg0 = g0c0;  pg1 = g0c1;                                                   \
        hpubA = hAn;                                                               \
        hpubB = hBn;                                                               \
    } while (0)

    // prologue: guarded (t0 < 0 for stage > r), fully unrolled (GUARD arms fold)
    #pragma unroll
    for (int r = 0; r < 5; ++r) ROUND(r, true);
    // steady + tail: select-free (zero-padded xs2 and wfc rows absorb overrun)
    #pragma unroll 4
    for (int r = 5; r < ROUNDS; ++r) ROUND(r, false);

    #undef ROUND
    #undef CELL

    // flush last round's deferred FC contribution (indices 618/619, valid)
    accA = fmaf(wA[2 * ROUNDS - 2], pg0, accA);
    accA = fmaf(wA[2 * ROUNDS - 1], pg1, accA);
    accB = fmaf(w4[2 * ROUNDS - 2], pg0, accB);
    accB = fmaf(w4[2 * ROUNDS - 1], pg1, accB);

    if (stage == 5) out[b * 5 + j] = accA;
    if (lane == 20) out[b * 5 + 4] = accB;
}

extern "C" void kernel_launch(void* const* d_in, const int* in_sizes, int n_in,
                              void* d_out, int out_size) {
    const float* x     = (const float*)d_in[0];
    const float* w_ih0 = (const float*)d_in[1];
    const float* w_ih  = (const float*)d_in[2];
    const float* w_hh  = (const float*)d_in[3];
    const float* b_ih  = (const float*)d_in[4];
    const float* b_hh  = (const float*)d_in[5];
    const float* w_lin = (const float*)d_in[6];
    const float* b_lin = (const float*)d_in[7];
    const float* w_fc  = (const float*)d_in[8];
    const float* b_fc  = (const float*)d_in[9];
    float* out = (float*)d_out;

    lstm_warp_kernel<<<BATCH, 32>>>(
        x, w_ih0, w_ih, w_hh, b_ih, b_hh, w_lin, b_lin, w_fc, b_fc, out);
}

// round 15
// speedup vs baseline: 1.1635x; 1.1635x over previous
#include <cuda_runtime.h>
#include <cuda_bf16.h>

// RNN_72541997629806: 5-layer stacked LSTM (H=4), SEQ=610, BATCH=128,
// per-t Linear(4->1) + final FC [5,610] -> out [128,5].
//
// R15: R13 champion skeleton (injection lanes + per-lane xinj + deferred FC
//   + MUFU order), with GATE-PAIR packed dots: accumulate (g2,g1) and
//   (g0,g3) as two fma.rn.f32x2 chains over duplicated scalar inputs.
//   16 fma2/cell replaces 24 fma-pipe ops (no add2/hadd); dups ride the
//   idle ALU pipe. One warp per batch element (128 x 32); 2 timesteps per
//   shuffle round; zero-padded SMEM; select-free steady loop.

#define SEQ 610
#define BATCH 128
#define ROUNDS 310           // r = 0..309 ; stage5 t1 = 2*309-10+1 = 609
#define XS_N 624
#define WFC_N 624            // valid data at [10, 620)

typedef unsigned long long ull;

__device__ __forceinline__ float tanh_fast(float x) {
    float y;
    asm("tanh.approx.f32 %0, %1;" : "=f"(y) : "f"(x));
    return y;
}
__device__ __forceinline__ ull pk2(float lo, float hi) {
    ull r; asm("mov.b64 %0, {%1, %2};" : "=l"(r) : "f"(lo), "f"(hi)); return r;
}
__device__ __forceinline__ ull dup2(float v) {
    ull r; asm("mov.b64 %0, {%1, %1};" : "=l"(r) : "f"(v)); return r;
}
__device__ __forceinline__ ull fma2(ull a, ull b, ull c) {
    ull d; asm("fma.rn.f32x2 %0, %1, %2, %3;" : "=l"(d) : "l"(a), "l"(b), "l"(c)); return d;
}
__device__ __forceinline__ void up2(ull v, float& lo, float& hi) {
    asm("mov.b64 {%0, %1}, %2;" : "=f"(lo), "=f"(hi) : "l"(v));
}

__global__ __launch_bounds__(32, 1)
void lstm_warp_kernel(const float* __restrict__ x,      // [128,610,2]
                      const float* __restrict__ w_ih0,  // [16,2]
                      const float* __restrict__ w_ih,   // [4,16,4]
                      const float* __restrict__ w_hh,   // [5,16,4]
                      const float* __restrict__ b_ih,   // [5,16]
                      const float* __restrict__ b_hh,   // [5,16]
                      const float* __restrict__ w_lin,  // [1,4]
                      const float* __restrict__ b_lin,  // [1]
                      const float* __restrict__ w_fc,   // [5,610]
                      const float* __restrict__ b_fc,   // [5]
                      float* __restrict__ out)          // [128,5]
{
    const int lane  = threadIdx.x;
    const int stage = lane >> 2;             // 0..7
    const int j     = lane & 3;
    const int b     = blockIdx.x;
    const int pbase = (lane - 4) & 28;       // base lane of previous stage quad
    const bool isX  = (lane >= 28);

    // ---- packed per-lane GATE-PAIR weights ----
    // Pair P = (g2 lo, g1 hi)  [g-gate, f-gate] — c-chain consumers first.
    // Pair Q = (g0 lo, g3 hi)  [i-gate, o-gate].
    // i/f/o columns pre-scaled by 0.5 (sigmoid-via-tanh).
    // wi*: absolute column order (p-quad arrives absolute via injection lanes);
    // wh*: j-relative columns (xor gather order).
    ull wiP0=0,wiP1=0,wiP2=0,wiP3=0, whP0=0,whP1=0,whP2=0,whP3=0;
    ull wiQ0=0,wiQ1=0,wiQ2=0,wiQ3=0, whQ0=0,whQ1=0,whQ2=0,whQ3=0;
    ull bpP=0, bpQ=0;

    if (stage <= 4) {
        float wv[4][4], hv[4][4], bv[4];
        #pragma unroll
        for (int q = 0; q < 4; ++q) {
            const int r = q * 4 + j;
            const float sc = (q == 2) ? 1.0f : 0.5f;
            #pragma unroll
            for (int d = 0; d < 4; ++d) {
                wv[q][d] = (stage == 0)
                    ? ((d < 2) ? sc * w_ih0[r * 2 + d] : 0.0f)
                    : sc * w_ih[(((stage - 1) * 16) + r) * 4 + d];
                hv[q][d] = sc * w_hh[((stage * 16) + r) * 4 + (j ^ d)];
            }
            bv[q] = sc * (b_ih[stage * 16 + r] + b_hh[stage * 16 + r]);
        }
        wiP0 = pk2(wv[2][0], wv[1][0]);  wiP1 = pk2(wv[2][1], wv[1][1]);
        wiP2 = pk2(wv[2][2], wv[1][2]);  wiP3 = pk2(wv[2][3], wv[1][3]);
        whP0 = pk2(hv[2][0], hv[1][0]);  whP1 = pk2(hv[2][1], hv[1][1]);
        whP2 = pk2(hv[2][2], hv[1][2]);  whP3 = pk2(hv[2][3], hv[1][3]);
        wiQ0 = pk2(wv[0][0], wv[3][0]);  wiQ1 = pk2(wv[0][1], wv[3][1]);
        wiQ2 = pk2(wv[0][2], wv[3][2]);  wiQ3 = pk2(wv[0][3], wv[3][3]);
        whQ0 = pk2(hv[0][0], hv[3][0]);  whQ1 = pk2(hv[0][1], hv[3][1]);
        whQ2 = pk2(hv[0][2], hv[3][2]);  whQ3 = pk2(hv[0][3], hv[3][3]);
        bpP  = pk2(bv[2], bv[1]);
        bpQ  = pk2(bv[0], bv[3]);
    } else if (stage == 5) {
        // g0 (lo half of pair Q) = Linear(4->1) pre-activation
        wiQ0 = pk2(w_lin[0], 0.0f);  wiQ1 = pk2(w_lin[1], 0.0f);
        wiQ2 = pk2(w_lin[2], 0.0f);  wiQ3 = pk2(w_lin[3], 0.0f);
        bpQ  = pk2(b_lin[0], 0.0f);
    }

    // ---- SMEM staging ----
    __shared__ float xinj[XS_N][4];         // per-lane injection: [ss][j]
    __shared__ float wfc_s[5][WFC_N];       // [10..619]=w_fc row, rest 0
    {
        const float2* xb2 = reinterpret_cast<const float2*>(x + (size_t)b * SEQ * 2);
        for (int i = lane; i < XS_N; i += 32) {
            const float2 v = (i < SEQ) ? xb2[i] : make_float2(0.0f, 0.0f);
            xinj[i][0] = v.x; xinj[i][1] = v.y;
            xinj[i][2] = 0.0f; xinj[i][3] = 0.0f;
        }
        #pragma unroll
        for (int r = 0; r < 5; ++r)
            for (int i = lane; i < WFC_N; i += 32)
                wfc_s[r][i] = (i >= 10 && i < SEQ + 10) ? w_fc[r * SEQ + (i - 10)] : 0.0f;
    }
    __syncwarp();

    const float* wA = wfc_s[(stage == 5) ? j : 0];
    const float* w4 = wfc_s[4];
    float accA = (stage == 5) ? b_fc[j] : 0.0f;
    float accB = (lane == 20) ? b_fc[4] : 0.0f;

    // ---- state ----
    float hpubA = isX ? xinj[0][j] : 0.0f;
    float hpubB = isX ? xinj[1][j] : 0.0f;
    float cj = 0.0f;
    float pg0 = 0.0f, pg1 = 0.0f;           // previous round's g0 values (deferred FC)

    // one LSTM cell, gate-pair packed dots; h terms last (h arrives latest)
    #define CELL(I0, I1, I2, I3, H0, H1, H2, H3, CN, HN, G0OUT) do {               \
        ull aP = fma2(wiP0, dup2(I0), bpP);                                        \
        ull aQ = fma2(wiQ0, dup2(I0), bpQ);                                        \
        aP = fma2(wiP1, dup2(I1), aP);  aQ = fma2(wiQ1, dup2(I1), aQ);             \
        aP = fma2(wiP2, dup2(I2), aP);  aQ = fma2(wiQ2, dup2(I2), aQ);             \
        aP = fma2(wiP3, dup2(I3), aP);  aQ = fma2(wiQ3, dup2(I3), aQ);             \
        aP = fma2(whP0, dup2(H0), aP);  aQ = fma2(whQ0, dup2(H0), aQ);             \
        aP = fma2(whP1, dup2(H1), aP);  aQ = fma2(whQ1, dup2(H1), aQ);             \
        aP = fma2(whP2, dup2(H2), aP);  aQ = fma2(whQ2, dup2(H2), aQ);             \
        aP = fma2(whP3, dup2(H3), aP);  aQ = fma2(whQ3, dup2(H3), aQ);             \
        float g2, g1, g0, g3;                                                      \
        up2(aP, g2, g1);                                                           \
        up2(aQ, g0, g3);                                                           \
        const float gt = tanh_fast(g2);                                            \
        const float fg = fmaf(0.5f, tanh_fast(g1), 0.5f);                          \
        const float ig = fmaf(0.5f, tanh_fast(g0), 0.5f);                          \
        const float og = fmaf(0.5f, tanh_fast(g3), 0.5f);                          \
        CN = fmaf(fg, cj, ig * gt);                                                \
        HN = og * tanh_fast(CN);                                                   \
        G0OUT = g0;                                                                \
    } while (0)

    // one round = two timesteps t0 = 2r - 2*stage, t1 = t0+1.
    // Order: shuffles -> (shadow) deferred FC of prev round + x loads -> cells.
    #define ROUND(r, GUARD) do {                                                   \
        const int i0 = 2 * (r);                                                    \
        /* round-start shuffles (all parallel off hpubA/hpubB) */                  \
        const float ob1 = __shfl_xor_sync(0xffffffffu, hpubB, 1);                  \
        const float ob2 = __shfl_xor_sync(0xffffffffu, hpubB, 2);                  \
        const float ob3 = __shfl_xor_sync(0xffffffffu, hpubB, 3);                  \
        const float pA0 = __shfl_sync(0xffffffffu, hpubA, pbase);                  \
        const float pA1 = __shfl_sync(0xffffffffu, hpubA, pbase + 1);              \
        const float pA2 = __shfl_sync(0xffffffffu, hpubA, pbase + 2);              \
        const float pA3 = __shfl_sync(0xffffffffu, hpubA, pbase + 3);              \
        const float pB0 = __shfl_sync(0xffffffffu, hpubB, pbase);                  \
        const float pB1 = __shfl_sync(0xffffffffu, hpubB, pbase + 1);              \
        const float pB2 = __shfl_sync(0xffffffffu, hpubB, pbase + 2);              \
        const float pB3 = __shfl_sync(0xffffffffu, hpubB, pbase + 3);              \
        /* shuffle shadow: deferred FC acc of PREVIOUS round + x loads */          \
        const int ip = GUARD ? ((r) > 0 ? i0 - 2 : 0) : (i0 - 2);                  \
        accA = fmaf(wA[ip],     pg0, accA);                                        \
        accA = fmaf(wA[ip + 1], pg1, accA);                                        \
        accB = fmaf(w4[ip],     pg0, accB);                                        \
        accB = fmaf(w4[ip + 1], pg1, accB);                                        \
        const float xcA = xinj[i0 + 2][j];                                         \
        const float xcB = xinj[i0 + 3][j];                                         \
        /* cell t0: own h quad = (hpubB, ob1..3) = h(t0-1) */                      \
        float cn0, hn0, g0c0;                                                      \
        CELL(pA0, pA1, pA2, pA3, hpubB, ob1, ob2, ob3, cn0, hn0, g0c0);            \
        float hAn;                                                                 \
        if (GUARD) {                                                               \
            const bool tv = (r) >= stage;                                          \
            cj  = tv ? cn0 : cj;                                                   \
            hAn = tv ? hn0 : 0.0f;                                                 \
        } else { cj = cn0; hAn = hn0; }                                            \
        /* intra-round gather of h(t0) */                                          \
        const float a1 = __shfl_xor_sync(0xffffffffu, hAn, 1);                     \
        const float a2 = __shfl_xor_sync(0xffffffffu, hAn, 2);                     \
        const float a3 = __shfl_xor_sync(0xffffffffu, hAn, 3);                     \
        /* cell t1 */                                                              \
        float cn1, hn1, g0c1;                                                      \
        CELL(pB0, pB1, pB2, pB3, hAn, a1, a2, a3, cn1, hn1, g0c1);                 \
        float hBn;                                                                 \
        if (GUARD) {                                                               \
            const bool tv = (r) >= stage;                                          \
            cj  = tv ? cn1 : cj;                                                   \
            hBn = tv ? hn1 : 0.0f;                                                 \
        } else { cj = cn1; hBn = hn1; }                                            \
        /* carry this round's g0s to the next round's shuffle shadow */            \
        pg0 = g0c0;  pg1 = g0c1;                                                   \
        hpubA = isX ? xcA : hAn;                                                   \
        hpubB = isX ? xcB : hBn;                                                   \
    } while (0)

    // prologue: guarded (t0 < 0 for stage > r), fully unrolled (GUARD arms fold)
    #pragma unroll
    for (int r = 0; r < 5; ++r) ROUND(r, true);
    // steady + tail: select-free (zero-padded xinj and wfc rows absorb overrun)
    #pragma unroll 4
    for (int r = 5; r < ROUNDS; ++r) ROUND(r, false);

    #undef ROUND
    #undef CELL

    // flush last round's deferred FC contribution (indices 618/619, valid)
    accA = fmaf(wA[2 * ROUNDS - 2], pg0, accA);
    accA = fmaf(wA[2 * ROUNDS - 1], pg1, accA);
    accB = fmaf(w4[2 * ROUNDS - 2], pg0, accB);
    accB = fmaf(w4[2 * ROUNDS - 1], pg1, accB);

    if (stage == 5) out[b * 5 + j] = accA;
    if (lane == 20) out[b * 5 + 4] = accB;
}

extern "C" void kernel_launch(void* const* d_in, const int* in_sizes, int n_in,
                              void* d_out, int out_size) {
    const float* x     = (const float*)d_in[0];
    const float* w_ih0 = (const float*)d_in[1];
    const float* w_ih  = (const float*)d_in[2];
    const float* w_hh  = (const float*)d_in[3];
    const float* b_ih  = (const float*)d_in[4];
    const float* b_hh  = (const float*)d_in[5];
    const float* w_lin = (const float*)d_in[6];
    const float* b_lin = (const float*)d_in[7];
    const float* w_fc  = (const float*)d_in[8];
    const float* b_fc  = (const float*)d_in[9];
    float* out = (float*)d_out;

    lstm_warp_kernel<<<BATCH, 32>>>(
        x, w_ih0, w_ih, w_hh, b_ih, b_hh, w_lin, b_lin, w_fc, b_fc, out);
}